// round 5
// baseline (speedup 1.0000x reference)
#include <cuda_runtime.h>
#include <cuda_bf16.h>

// PPO loss, single fused kernel with cp.async overlap.
// Reverse GAE + value-target recurrences are effectively local (0.99^2048 ~ 1.2e-9):
// each block independently produces OUT_CHUNK outputs. probs/probs_old are
// prefetched to SMEM via cp.async at kernel entry so their DRAM traffic overlaps
// the (memory-idle) scan phase; r/v stream to registers as float4; advantages
// parked in SMEM for the coalesced clip/entropy pass; last-block final reduce.

#define PPO_EPS    0.2f
#define PPO_GAMMA  0.99f
#define PPO_A1     (0.99f * 0.95f)   // gamma * lambda
#define PPO_C1     0.5f
#define PPO_C2     0.01f

#define THREADS    512
#define SEG        20                     // elements per thread
#define ELEMS      (THREADS * SEG)        // 10240 = chunk + halo
#define OUT_CHUNK  8192                   // outputs per block (halo = 2048)

// advantages in padded layout pi(i)=i+i/SEG (stride-21 per thread, conflict-free)
#define ADV_WORDS  8608                   // > pi(OUT_CHUNK-1) = 8600
// dynamic SMEM floats: p_s + po_s + adv + sg + sv
#define SM_P    0
#define SM_PO   (SM_P  + OUT_CHUNK)
#define SM_ADV  (SM_PO + OUT_CHUNK)
#define SM_SG   (SM_ADV + ADV_WORDS)
#define SM_SV   (SM_SG + THREADS)
#define SM_TOTAL (SM_SV + THREADS)        // 26016 floats = 104064 B

__device__ float g_partials[4096];
__device__ unsigned int g_count = 0;

__host__ __device__ constexpr double dpow(double b, int n) {
    double r = 1.0;
    for (int i = 0; i < n; ++i) r *= b;
    return r;
}
#define FG0 ((float)dpow((double)PPO_A1,    SEG))   // a1^20
#define FV0 ((float)dpow((double)PPO_GAMMA, SEG))   // gamma^20

__global__ __launch_bounds__(THREADS, 2)
void ppo_fused(const float* __restrict__ probs,
               const float* __restrict__ probs_old,
               const float* __restrict__ rewards,
               const float* __restrict__ values,
               float* __restrict__ out,
               int T)
{
    extern __shared__ float smf[];
    float* p_s  = smf + SM_P;
    float* po_s = smf + SM_PO;
    float* adv  = smf + SM_ADV;
    float* sg   = smf + SM_SG;
    float* sv   = smf + SM_SV;
    __shared__ unsigned int s_last;

    const int tid = threadIdx.x;
    const long long s = (long long)blockIdx.x * OUT_CHUNK;
    const long long gbase = s + (long long)tid * SEG;
    const bool full = (s + OUT_CHUNK) <= (long long)T;

    // ---- Prefetch probs/probs_old to SMEM (cp.async, overlaps the scan) ----
    if (full) {
        const float* pg  = probs + s;
        const float* pog = probs_old + s;
        #pragma unroll
        for (int k = 0; k < OUT_CHUNK / (4 * THREADS); ++k) {   // 4 chunks/array
            int idx = (tid + k * THREADS) * 4;                  // 16B-aligned
            unsigned int sp = (unsigned int)__cvta_generic_to_shared(p_s + idx);
            asm volatile("cp.async.cg.shared.global [%0], [%1], 16;\n"
                         :: "r"(sp), "l"(pg + idx));
            unsigned int sp2 = (unsigned int)__cvta_generic_to_shared(po_s + idx);
            asm volatile("cp.async.cg.shared.global [%0], [%1], 16;\n"
                         :: "r"(sp2), "l"(pog + idx));
        }
        asm volatile("cp.async.commit_group;\n");
    }

    // ---- Load this thread's segment (20 r, 20 v, 1 lookahead v) into registers ----
    float r[SEG], v[SEG], vNext;
    if (gbase + SEG < (long long)T) {           // fast path: fully in range
        #pragma unroll
        for (int k = 0; k < SEG / 4; ++k) {
            float4 r4 = *reinterpret_cast<const float4*>(rewards + gbase + 4 * k);
            float4 v4 = *reinterpret_cast<const float4*>(values  + gbase + 4 * k);
            r[4*k+0] = r4.x; r[4*k+1] = r4.y; r[4*k+2] = r4.z; r[4*k+3] = r4.w;
            v[4*k+0] = v4.x; v[4*k+1] = v4.y; v[4*k+2] = v4.z; v[4*k+3] = v4.w;
        }
        vNext = values[gbase + SEG];
    } else {                                    // tail: guarded scalar
        #pragma unroll
        for (int i = 0; i < SEG; ++i) {
            long long gi = gbase + i;
            bool ok = gi < (long long)T;
            r[i] = ok ? rewards[gi] : 0.0f;
            v[i] = ok ? values[gi]  : 0.0f;
        }
        vNext = 0.0f;                           // gbase+SEG >= T here
    }

    // ---- Per-thread reverse aggregates over the segment ----
    float Lg = 0.0f, Lv = 0.0f;
    {
        float vn = vNext;
        #pragma unroll
        for (int i = SEG - 1; i >= 0; --i) {
            float delta = r[i] - v[i] + PPO_GAMMA * vn;
            Lg = fmaf(PPO_A1,    Lg, delta);
            Lv = fmaf(PPO_GAMMA, Lv, r[i]);
            vn = v[i];
        }
    }
    sg[tid] = Lg;
    sv[tid] = Lv;
    __syncthreads();

    // ---- Block-level reverse inclusive scan (Hillis-Steele, uniform factors) ----
    float Fg = FG0, Fv = FV0;
    float vg = Lg, vvt = Lv;
    #pragma unroll
    for (int off = 1; off < THREADS; off <<= 1) {
        float ag = 0.0f, av = 0.0f;
        if (tid + off < THREADS) { ag = sg[tid + off]; av = sv[tid + off]; }
        __syncthreads();
        vg  = fmaf(Fg, ag, vg);
        vvt = fmaf(Fv, av, vvt);
        sg[tid] = vg;
        sv[tid] = vvt;
        Fg *= Fg; Fv *= Fv;
        __syncthreads();
    }
    float Eg = (tid + 1 < THREADS) ? sg[tid + 1] : 0.0f;  // carry into segment end
    float Ev = (tid + 1 < THREADS) ? sv[tid + 1] : 0.0f;

    // ---- Recompute with carry: value loss in regs, advantages -> SMEM ----
    const int baseL = tid * SEG;
    const int baseP = baseL + tid;   // == pi(baseL), 21*tid
    float s_vl = 0.0f;
    {
        float g = Eg, V = Ev, vn = vNext;
        #pragma unroll
        for (int i = SEG - 1; i >= 0; --i) {
            float delta = r[i] - v[i] + PPO_GAMMA * vn;
            g = fmaf(PPO_A1,    g, delta);
            V = fmaf(PPO_GAMMA, V, r[i]);
            vn = v[i];
            if (baseL + i < OUT_CHUNK) {
                float d = v[i] - V;
                s_vl = fmaf(d, d, s_vl);
                adv[baseP + i] = g;
            }
        }
    }
    if (full) asm volatile("cp.async.wait_group 0;\n" ::: "memory");
    __syncthreads();   // adv + prefetched probs visible

    // ---- Clip/entropy pass ----
    float s_clip = 0.0f, s_ent = 0.0f;
    if (full) {
        const float4* p4p  = reinterpret_cast<const float4*>(p_s);
        const float4* po4p = reinterpret_cast<const float4*>(po_s);
        #pragma unroll 2
        for (int k = tid; k < OUT_CHUNK / 4; k += THREADS) {
            float4 p4 = p4p[k];
            float4 o4 = po4p[k];
            float pv[4] = {p4.x, p4.y, p4.z, p4.w};
            float ov[4] = {o4.x, o4.y, o4.z, o4.w};
            int li = 4 * k;
            #pragma unroll
            for (int c = 0; c < 4; ++c) {
                int j = li + c;
                float a = adv[j + j / SEG];
                float ratio = __fdividef(pv[c], ov[c]);
                float cl = fminf(fmaxf(ratio, 1.0f - PPO_EPS), 1.0f + PPO_EPS);
                s_clip += fminf(ratio * a, cl * a);
                s_ent   = fmaf(pv[c], __logf(pv[c] + 1e-5f), s_ent);
            }
        }
    } else {
        long long left = (long long)T - s;
        int rem = (left < (long long)OUT_CHUNK) ? (int)left : OUT_CHUNK;
        for (int j = tid; j < rem; j += THREADS) {
            float p  = probs[s + j];
            float po = probs_old[s + j];
            float a  = adv[j + j / SEG];
            float ratio = __fdividef(p, po);
            float cl = fminf(fmaxf(ratio, 1.0f - PPO_EPS), 1.0f + PPO_EPS);
            s_clip += fminf(ratio * a, cl * a);
            s_ent   = fmaf(p, __logf(p + 1e-5f), s_ent);
        }
    }

    // total = -s_clip + C1*s_vl - C2*s_ent
    float part = -s_clip + PPO_C1 * s_vl - PPO_C2 * s_ent;

    // ---- Block tree reduction (reuse sg) ----
    sg[tid] = part;
    __syncthreads();
    #pragma unroll
    for (int off = THREADS / 2; off > 0; off >>= 1) {
        if (tid < off) sg[tid] += sg[tid + off];
        __syncthreads();
    }

    // ---- Last-block final reduction (deterministic fixed-order sum) ----
    if (tid == 0) {
        g_partials[blockIdx.x] = sg[0];
        __threadfence();
        unsigned int prev = atomicInc(&g_count, gridDim.x - 1);  // wraps to 0
        s_last = (prev == gridDim.x - 1) ? 1u : 0u;
    }
    __syncthreads();
    if (s_last) {
        __threadfence();
        float x = 0.0f;
        for (int i = tid; i < (int)gridDim.x; i += THREADS) x += g_partials[i];
        sg[tid] = x;
        __syncthreads();
        #pragma unroll
        for (int off = THREADS / 2; off > 0; off >>= 1) {
            if (tid < off) sg[tid] += sg[tid + off];
            __syncthreads();
        }
        if (tid == 0) out[0] = sg[0];
    }
}

extern "C" void kernel_launch(void* const* d_in, const int* in_sizes, int n_in,
                              void* d_out, int out_size)
{
    const float* probs     = (const float*)d_in[0];
    const float* probs_old = (const float*)d_in[1];
    const float* rewards   = (const float*)d_in[2];
    const float* values    = (const float*)d_in[3];
    int T = in_sizes[0];

    int nblocks = (T + OUT_CHUNK - 1) / OUT_CHUNK;
    if (nblocks > 4096) nblocks = 4096;   // g_partials capacity (T=2^23 -> 1024)

    size_t smem_bytes = (size_t)SM_TOTAL * sizeof(float);
    cudaFuncSetAttribute(ppo_fused, cudaFuncAttributeMaxDynamicSharedMemorySize,
                         (int)smem_bytes);

    ppo_fused<<<nblocks, THREADS, smem_bytes>>>(probs, probs_old, rewards, values,
                                                (float*)d_out, T);
}

// round 6
// speedup vs baseline: 1.5524x; 1.5524x over previous
#include <cuda_runtime.h>
#include <cuda_bf16.h>

// PPO loss, single fused kernel (R4 base + L2-prefetch overlap + shuffle scans).
// Reverse GAE/value-target recurrences are local (0.99^2048 ~ 1.2e-9): each block
// independently produces OUT_CHUNK outputs from register-resident float4 segments
// with a 2048-element halo. probs/probs_old are pulled into L2 via one
// prefetch.global.L2 per thread (issued AFTER the critical-path r/v loads) so
// their DRAM traffic overlaps the scan. Block scan is shfl-based (2 barriers).

#define PPO_EPS    0.2f
#define PPO_GAMMA  0.99f
#define PPO_A1     (0.99f * 0.95f)   // gamma * lambda
#define PPO_C1     0.5f
#define PPO_C2     0.01f

#define THREADS    512
#define NWARP      (THREADS / 32)
#define SEG        20                     // elements per thread (80B: float4-aligned)
#define OUT_CHUNK  8192                   // outputs per block (halo = 2048)

// advantages in padded layout pi(i)=i+i/SEG (stride-21 per thread, conflict-free)
#define ADV_WORDS  8608                   // > pi(OUT_CHUNK-1) = 8600

__device__ float g_partials[4096];
__device__ unsigned int g_count = 0;

__host__ __device__ constexpr double dpow(double b, int n) {
    double r = 1.0;
    for (int i = 0; i < n; ++i) r *= b;
    return r;
}
// per-segment factors and their power-of-two ladder (exact compile-time doubles)
#define FG0  ((float)dpow((double)PPO_A1,    SEG))       // a1^20
#define FV0  ((float)dpow((double)PPO_GAMMA, SEG))       // g^20
#define CG(k) ((float)dpow((double)PPO_A1,    SEG << (k)))
#define CV(k) ((float)dpow((double)PPO_GAMMA, SEG << (k)))
#define FWG0 ((float)dpow((double)PPO_A1,    SEG * 32))  // a1^640
#define FWV0 ((float)dpow((double)PPO_GAMMA, SEG * 32))  // g^640

__global__ __launch_bounds__(THREADS, 2)
void ppo_fused(const float* __restrict__ probs,
               const float* __restrict__ probs_old,
               const float* __restrict__ rewards,
               const float* __restrict__ values,
               float* __restrict__ out,
               int T)
{
    __shared__ float adv[ADV_WORDS];
    __shared__ float wtg[NWARP], wtv[NWARP];   // warp totals
    __shared__ float wcg[NWARP], wcv[NWARP];   // warp carries
    __shared__ unsigned int s_last;

    const int tid  = threadIdx.x;
    const int lane = tid & 31;
    const int w    = tid >> 5;
    const long long s = (long long)blockIdx.x * OUT_CHUNK;
    const long long gbase = s + (long long)tid * SEG;
    const bool full = (s + OUT_CHUNK) <= (long long)T;

    // ---- Load this thread's segment (critical path) into registers ----
    float r[SEG], v[SEG], vNext;
    if (gbase + SEG < (long long)T) {
        #pragma unroll
        for (int k = 0; k < SEG / 4; ++k) {
            float4 r4 = *reinterpret_cast<const float4*>(rewards + gbase + 4 * k);
            float4 v4 = *reinterpret_cast<const float4*>(values  + gbase + 4 * k);
            r[4*k+0] = r4.x; r[4*k+1] = r4.y; r[4*k+2] = r4.z; r[4*k+3] = r4.w;
            v[4*k+0] = v4.x; v[4*k+1] = v4.y; v[4*k+2] = v4.z; v[4*k+3] = v4.w;
        }
        vNext = values[gbase + SEG];
    } else {
        #pragma unroll
        for (int i = 0; i < SEG; ++i) {
            long long gi = gbase + i;
            bool ok = gi < (long long)T;
            r[i] = ok ? rewards[gi] : 0.0f;
            v[i] = ok ? values[gi]  : 0.0f;
        }
        vNext = 0.0f;
    }

    // ---- L2 prefetch of this block's probs/probs_old (AFTER r/v issue) ----
    // 512 threads x 128B lines = 64KB = both 32KB arrays exactly.
    if (full) {
        const char* base = (tid < 256)
            ? (const char*)(probs + s)     + (size_t)tid * 128
            : (const char*)(probs_old + s) + (size_t)(tid - 256) * 128;
        asm volatile("prefetch.global.L2 [%0];" :: "l"(base));
    }

    // ---- Per-thread reverse aggregates over the segment ----
    float Lg = 0.0f, Lv = 0.0f;
    {
        float vn = vNext;
        #pragma unroll
        for (int i = SEG - 1; i >= 0; --i) {
            float delta = r[i] - v[i] + PPO_GAMMA * vn;
            Lg = fmaf(PPO_A1,    Lg, delta);
            Lv = fmaf(PPO_GAMMA, Lv, r[i]);
            vn = v[i];
        }
    }

    // ---- Warp-level reverse inclusive scan (shfl, factor squaring) ----
    float Sg = Lg, Sv = Lv, Fg = FG0, Fv = FV0;
    #pragma unroll
    for (int off = 1; off < 32; off <<= 1) {
        float og = __shfl_down_sync(0xffffffffu, Sg, off);
        float ov = __shfl_down_sync(0xffffffffu, Sv, off);
        if (lane + off < 32) { Sg = fmaf(Fg, og, Sg); Sv = fmaf(Fv, ov, Sv); }
        Fg *= Fg; Fv *= Fv;
    }
    float eg = __shfl_down_sync(0xffffffffu, Sg, 1);   // within-warp carry S_{l+1}
    float ev = __shfl_down_sync(0xffffffffu, Sv, 1);
    if (lane == 31) { eg = 0.0f; ev = 0.0f; }
    if (lane == 0) { wtg[w] = Sg; wtv[w] = Sv; }       // warp totals
    __syncthreads();

    // ---- Warp 0 scans the 16 warp totals (factor a^(SEG*32)) ----
    if (w == 0) {
        float tg = (lane < NWARP) ? wtg[lane] : 0.0f;
        float tv = (lane < NWARP) ? wtv[lane] : 0.0f;
        float FWg = FWG0, FWv = FWV0;
        #pragma unroll
        for (int off = 1; off < NWARP; off <<= 1) {
            float og = __shfl_down_sync(0xffffffffu, tg, off);
            float ov = __shfl_down_sync(0xffffffffu, tv, off);
            if (lane + off < NWARP) { tg = fmaf(FWg, og, tg); tv = fmaf(FWv, ov, tv); }
            FWg *= FWg; FWv *= FWv;
        }
        float cg = __shfl_down_sync(0xffffffffu, tg, 1);
        float cv = __shfl_down_sync(0xffffffffu, tv, 1);
        if (lane == NWARP - 1) { cg = 0.0f; cv = 0.0f; }
        if (lane < NWARP) { wcg[lane] = cg; wcv[lane] = cv; }
    }
    __syncthreads();

    // ---- Per-lane carry: E = S_{l+1} + a^(SEG*(31-l)) * warpCarry ----
    float facg = 1.0f, facv = 1.0f;
    {
        int m = 31 - lane;
        if (m & 1)  { facg *= CG(0); facv *= CV(0); }
        if (m & 2)  { facg *= CG(1); facv *= CV(1); }
        if (m & 4)  { facg *= CG(2); facv *= CV(2); }
        if (m & 8)  { facg *= CG(3); facv *= CV(3); }
        if (m & 16) { facg *= CG(4); facv *= CV(4); }
    }
    float Eg = fmaf(facg, wcg[w], eg);
    float Ev = fmaf(facv, wcv[w], ev);

    // ---- Recompute with carry: value loss in regs, advantages -> SMEM ----
    const int baseL = tid * SEG;
    const int baseP = baseL + tid;   // == 21*tid (padded layout)
    float s_vl = 0.0f;
    {
        float g = Eg, V = Ev, vn = vNext;
        #pragma unroll
        for (int i = SEG - 1; i >= 0; --i) {
            float delta = r[i] - v[i] + PPO_GAMMA * vn;
            g = fmaf(PPO_A1,    g, delta);
            V = fmaf(PPO_GAMMA, V, r[i]);
            vn = v[i];
            if (baseL + i < OUT_CHUNK) {
                float d = v[i] - V;
                s_vl = fmaf(d, d, s_vl);
                adv[baseP + i] = g;
            }
        }
    }
    __syncthreads();   // adv visible

    // ---- Coalesced probs pass (L2-hit after prefetch) ----
    float s_clip = 0.0f, s_ent = 0.0f;
    if (full) {
        const float4* p4p  = reinterpret_cast<const float4*>(probs + s);
        const float4* po4p = reinterpret_cast<const float4*>(probs_old + s);
        #pragma unroll
        for (int it = 0; it < OUT_CHUNK / (4 * THREADS); ++it) {
            int k = tid + it * THREADS;
            float4 p4 = p4p[k];
            float4 o4 = po4p[k];
            float pv[4] = {p4.x, p4.y, p4.z, p4.w};
            float ov[4] = {o4.x, o4.y, o4.z, o4.w};
            int li = 4 * k;
            #pragma unroll
            for (int c = 0; c < 4; ++c) {
                int j = li + c;
                float a = adv[j + j / SEG];
                float ratio = __fdividef(pv[c], ov[c]);
                float cl = fminf(fmaxf(ratio, 1.0f - PPO_EPS), 1.0f + PPO_EPS);
                s_clip += fminf(ratio * a, cl * a);
                s_ent   = fmaf(pv[c], __logf(pv[c] + 1e-5f), s_ent);
            }
        }
    } else {
        long long left = (long long)T - s;
        int rem = (left < (long long)OUT_CHUNK) ? (int)left : OUT_CHUNK;
        for (int j = tid; j < rem; j += THREADS) {
            float p  = probs[s + j];
            float po = probs_old[s + j];
            float a  = adv[j + j / SEG];
            float ratio = __fdividef(p, po);
            float cl = fminf(fmaxf(ratio, 1.0f - PPO_EPS), 1.0f + PPO_EPS);
            s_clip += fminf(ratio * a, cl * a);
            s_ent   = fmaf(p, __logf(p + 1e-5f), s_ent);
        }
    }

    // total = -s_clip + C1*s_vl - C2*s_ent
    float part = -s_clip + PPO_C1 * s_vl - PPO_C2 * s_ent;

    // ---- Block reduction (shuffle + one smem hop) ----
    #pragma unroll
    for (int off = 16; off > 0; off >>= 1)
        part += __shfl_xor_sync(0xffffffffu, part, off);
    if (lane == 0) wtg[w] = part;
    __syncthreads();
    if (w == 0) {
        float y = (lane < NWARP) ? wtg[lane] : 0.0f;
        #pragma unroll
        for (int off = NWARP / 2; off > 0; off >>= 1)
            y += __shfl_xor_sync(0xffffffffu, y, off);
        if (lane == 0) {
            g_partials[blockIdx.x] = y;
            __threadfence();
            unsigned int prev = atomicInc(&g_count, gridDim.x - 1);  // wraps to 0
            s_last = (prev == gridDim.x - 1) ? 1u : 0u;
        }
    }
    __syncthreads();

    // ---- Last block: deterministic final sum ----
    if (s_last) {
        __threadfence();
        float x = 0.0f;
        for (int i = tid; i < (int)gridDim.x; i += THREADS) x += g_partials[i];
        #pragma unroll
        for (int off = 16; off > 0; off >>= 1)
            x += __shfl_xor_sync(0xffffffffu, x, off);
        if (lane == 0) wtv[w] = x;
        __syncthreads();
        if (w == 0) {
            float y = (lane < NWARP) ? wtv[lane] : 0.0f;
            #pragma unroll
            for (int off = NWARP / 2; off > 0; off >>= 1)
                y += __shfl_xor_sync(0xffffffffu, y, off);
            if (lane == 0) out[0] = y;
        }
    }
}

extern "C" void kernel_launch(void* const* d_in, const int* in_sizes, int n_in,
                              void* d_out, int out_size)
{
    const float* probs     = (const float*)d_in[0];
    const float* probs_old = (const float*)d_in[1];
    const float* rewards   = (const float*)d_in[2];
    const float* values    = (const float*)d_in[3];
    int T = in_sizes[0];

    int nblocks = (T + OUT_CHUNK - 1) / OUT_CHUNK;
    if (nblocks > 4096) nblocks = 4096;   // g_partials capacity (T=2^23 -> 1024)

    ppo_fused<<<nblocks, THREADS>>>(probs, probs_old, rewards, values,
                                    (float*)d_out, T);
}

// round 7
// speedup vs baseline: 1.6439x; 1.0590x over previous
#include <cuda_runtime.h>
#include <cuda_bf16.h>

// PPO loss, single fused kernel. R6 base re-tiled to 4 CTAs x 256 threads per SM
// for phase diversity (DRAM stays busy while sibling CTAs compute).
// Reverse GAE/value-target recurrences are local (0.99^1024 ~ 3.4e-5): each block
// independently produces OUT_CHUNK outputs from register-resident float4 segments
// with a 1024-element halo. probs/probs_old pulled into L2 via prefetch.global.L2
// (issued AFTER critical-path r/v loads). Shfl-based block scan, last-block reduce.

#define PPO_EPS    0.2f
#define PPO_GAMMA  0.99f
#define PPO_A1     (0.99f * 0.95f)   // gamma * lambda
#define PPO_C1     0.5f
#define PPO_C2     0.01f

#define THREADS    256
#define NWARP      (THREADS / 32)          // 8
#define SEG        20                      // elements per thread (80B, float4-aligned)
#define ELEMS      (THREADS * SEG)         // 5120 = chunk + halo
#define OUT_CHUNK  4096                    // outputs per block (halo = 1024)

// advantages in padded layout pi(i)=i+i/SEG (stride-21 per thread, conflict-free)
#define ADV_WORDS  4304                    // > pi(OUT_CHUNK-1) = 4299

__device__ float g_partials[4096];
__device__ unsigned int g_count = 0;

__host__ __device__ constexpr double dpow(double b, int n) {
    double r = 1.0;
    for (int i = 0; i < n; ++i) r *= b;
    return r;
}
#define FG0  ((float)dpow((double)PPO_A1,    SEG))       // a1^20
#define FV0  ((float)dpow((double)PPO_GAMMA, SEG))       // g^20
#define CG(k) ((float)dpow((double)PPO_A1,    SEG << (k)))
#define CV(k) ((float)dpow((double)PPO_GAMMA, SEG << (k)))
#define FWG0 ((float)dpow((double)PPO_A1,    SEG * 32))  // a1^640
#define FWV0 ((float)dpow((double)PPO_GAMMA, SEG * 32))  // g^640

__global__ __launch_bounds__(THREADS, 4)
void ppo_fused(const float* __restrict__ probs,
               const float* __restrict__ probs_old,
               const float* __restrict__ rewards,
               const float* __restrict__ values,
               float* __restrict__ out,
               int T)
{
    __shared__ float adv[ADV_WORDS];
    __shared__ float wtg[NWARP], wtv[NWARP];   // warp totals
    __shared__ float wcg[NWARP], wcv[NWARP];   // warp carries
    __shared__ unsigned int s_last;

    const int tid  = threadIdx.x;
    const int lane = tid & 31;
    const int w    = tid >> 5;
    const long long s = (long long)blockIdx.x * OUT_CHUNK;
    const long long gbase = s + (long long)tid * SEG;
    const bool full = (s + OUT_CHUNK) <= (long long)T;

    // ---- Load this thread's segment (critical path) into registers ----
    float r[SEG], v[SEG], vNext;
    if (gbase + SEG < (long long)T) {
        #pragma unroll
        for (int k = 0; k < SEG / 4; ++k) {
            float4 r4 = *reinterpret_cast<const float4*>(rewards + gbase + 4 * k);
            float4 v4 = *reinterpret_cast<const float4*>(values  + gbase + 4 * k);
            r[4*k+0] = r4.x; r[4*k+1] = r4.y; r[4*k+2] = r4.z; r[4*k+3] = r4.w;
            v[4*k+0] = v4.x; v[4*k+1] = v4.y; v[4*k+2] = v4.z; v[4*k+3] = v4.w;
        }
        vNext = values[gbase + SEG];
    } else {
        #pragma unroll
        for (int i = 0; i < SEG; ++i) {
            long long gi = gbase + i;
            bool ok = gi < (long long)T;
            r[i] = ok ? rewards[gi] : 0.0f;
            v[i] = ok ? values[gi]  : 0.0f;
        }
        vNext = 0.0f;
    }

    // ---- L2 prefetch of this block's probs/probs_old (AFTER r/v issue) ----
    // 256 threads x 128B lines = 32KB = both 16KB arrays exactly.
    if (full) {
        const char* base = (tid < 128)
            ? (const char*)(probs + s)     + (size_t)tid * 128
            : (const char*)(probs_old + s) + (size_t)(tid - 128) * 128;
        asm volatile("prefetch.global.L2 [%0];" :: "l"(base));
    }

    // ---- Per-thread reverse aggregates over the segment ----
    float Lg = 0.0f, Lv = 0.0f;
    {
        float vn = vNext;
        #pragma unroll
        for (int i = SEG - 1; i >= 0; --i) {
            float delta = r[i] - v[i] + PPO_GAMMA * vn;
            Lg = fmaf(PPO_A1,    Lg, delta);
            Lv = fmaf(PPO_GAMMA, Lv, r[i]);
            vn = v[i];
        }
    }

    // ---- Warp-level reverse inclusive scan (shfl, factor squaring) ----
    float Sg = Lg, Sv = Lv, Fg = FG0, Fv = FV0;
    #pragma unroll
    for (int off = 1; off < 32; off <<= 1) {
        float og = __shfl_down_sync(0xffffffffu, Sg, off);
        float ov = __shfl_down_sync(0xffffffffu, Sv, off);
        if (lane + off < 32) { Sg = fmaf(Fg, og, Sg); Sv = fmaf(Fv, ov, Sv); }
        Fg *= Fg; Fv *= Fv;
    }
    float eg = __shfl_down_sync(0xffffffffu, Sg, 1);   // within-warp carry S_{l+1}
    float ev = __shfl_down_sync(0xffffffffu, Sv, 1);
    if (lane == 31) { eg = 0.0f; ev = 0.0f; }
    if (lane == 0) { wtg[w] = Sg; wtv[w] = Sv; }       // warp totals
    __syncthreads();

    // ---- Warp 0 scans the NWARP warp totals (factor a^(SEG*32)) ----
    if (w == 0) {
        float tg = (lane < NWARP) ? wtg[lane] : 0.0f;
        float tv = (lane < NWARP) ? wtv[lane] : 0.0f;
        float FWg = FWG0, FWv = FWV0;
        #pragma unroll
        for (int off = 1; off < NWARP; off <<= 1) {
            float og = __shfl_down_sync(0xffffffffu, tg, off);
            float ov = __shfl_down_sync(0xffffffffu, tv, off);
            if (lane + off < NWARP) { tg = fmaf(FWg, og, tg); tv = fmaf(FWv, ov, tv); }
            FWg *= FWg; FWv *= FWv;
        }
        float cg = __shfl_down_sync(0xffffffffu, tg, 1);
        float cv = __shfl_down_sync(0xffffffffu, tv, 1);
        if (lane == NWARP - 1) { cg = 0.0f; cv = 0.0f; }
        if (lane < NWARP) { wcg[lane] = cg; wcv[lane] = cv; }
    }
    __syncthreads();

    // ---- Per-lane carry: E = S_{l+1} + a^(SEG*(31-l)) * warpCarry ----
    float facg = 1.0f, facv = 1.0f;
    {
        int m = 31 - lane;
        if (m & 1)  { facg *= CG(0); facv *= CV(0); }
        if (m & 2)  { facg *= CG(1); facv *= CV(1); }
        if (m & 4)  { facg *= CG(2); facv *= CV(2); }
        if (m & 8)  { facg *= CG(3); facv *= CV(3); }
        if (m & 16) { facg *= CG(4); facv *= CV(4); }
    }
    float Eg = fmaf(facg, wcg[w], eg);
    float Ev = fmaf(facv, wcv[w], ev);

    // ---- Recompute with carry: value loss in regs, advantages -> SMEM ----
    const int baseL = tid * SEG;
    const int baseP = baseL + tid;   // == 21*tid (padded layout)
    float s_vl = 0.0f;
    {
        float g = Eg, V = Ev, vn = vNext;
        #pragma unroll
        for (int i = SEG - 1; i >= 0; --i) {
            float delta = r[i] - v[i] + PPO_GAMMA * vn;
            g = fmaf(PPO_A1,    g, delta);
            V = fmaf(PPO_GAMMA, V, r[i]);
            vn = v[i];
            if (baseL + i < OUT_CHUNK) {
                float d = v[i] - V;
                s_vl = fmaf(d, d, s_vl);
                adv[baseP + i] = g;
            }
        }
    }
    __syncthreads();   // adv visible

    // ---- Coalesced probs pass (L2-hit after prefetch) ----
    float s_clip = 0.0f, s_ent = 0.0f;
    if (full) {
        const float4* p4p  = reinterpret_cast<const float4*>(probs + s);
        const float4* po4p = reinterpret_cast<const float4*>(probs_old + s);
        #pragma unroll
        for (int it = 0; it < OUT_CHUNK / (4 * THREADS); ++it) {
            int k = tid + it * THREADS;
            float4 p4 = p4p[k];
            float4 o4 = po4p[k];
            float pv[4] = {p4.x, p4.y, p4.z, p4.w};
            float ov[4] = {o4.x, o4.y, o4.z, o4.w};
            int li = 4 * k;
            #pragma unroll
            for (int c = 0; c < 4; ++c) {
                int j = li + c;
                float a = adv[j + j / SEG];
                float ratio = __fdividef(pv[c], ov[c]);
                float cl = fminf(fmaxf(ratio, 1.0f - PPO_EPS), 1.0f + PPO_EPS);
                s_clip += fminf(ratio * a, cl * a);
                s_ent   = fmaf(pv[c], __logf(pv[c] + 1e-5f), s_ent);
            }
        }
    } else {
        long long left = (long long)T - s;
        int rem = (left < (long long)OUT_CHUNK) ? (int)left : OUT_CHUNK;
        for (int j = tid; j < rem; j += THREADS) {
            float p  = probs[s + j];
            float po = probs_old[s + j];
            float a  = adv[j + j / SEG];
            float ratio = __fdividef(p, po);
            float cl = fminf(fmaxf(ratio, 1.0f - PPO_EPS), 1.0f + PPO_EPS);
            s_clip += fminf(ratio * a, cl * a);
            s_ent   = fmaf(p, __logf(p + 1e-5f), s_ent);
        }
    }

    // total = -s_clip + C1*s_vl - C2*s_ent
    float part = -s_clip + PPO_C1 * s_vl - PPO_C2 * s_ent;

    // ---- Block reduction (shuffle + one smem hop) ----
    #pragma unroll
    for (int off = 16; off > 0; off >>= 1)
        part += __shfl_xor_sync(0xffffffffu, part, off);
    if (lane == 0) wtg[w] = part;
    __syncthreads();
    if (w == 0) {
        float y = (lane < NWARP) ? wtg[lane] : 0.0f;
        #pragma unroll
        for (int off = NWARP / 2; off > 0; off >>= 1)
            y += __shfl_xor_sync(0xffffffffu, y, off);
        if (lane == 0) {
            g_partials[blockIdx.x] = y;
            __threadfence();
            unsigned int prev = atomicInc(&g_count, gridDim.x - 1);  // wraps to 0
            s_last = (prev == gridDim.x - 1) ? 1u : 0u;
        }
    }
    __syncthreads();

    // ---- Last block: deterministic final sum ----
    if (s_last) {
        __threadfence();
        float x = 0.0f;
        for (int i = tid; i < (int)gridDim.x; i += THREADS) x += g_partials[i];
        #pragma unroll
        for (int off = 16; off > 0; off >>= 1)
            x += __shfl_xor_sync(0xffffffffu, x, off);
        if (lane == 0) wtv[w] = x;
        __syncthreads();
        if (w == 0) {
            float y = (lane < NWARP) ? wtv[lane] : 0.0f;
            #pragma unroll
            for (int off = NWARP / 2; off > 0; off >>= 1)
                y += __shfl_xor_sync(0xffffffffu, y, off);
            if (lane == 0) out[0] = y;
        }
    }
}

extern "C" void kernel_launch(void* const* d_in, const int* in_sizes, int n_in,
                              void* d_out, int out_size)
{
    const float* probs     = (const float*)d_in[0];
    const float* probs_old = (const float*)d_in[1];
    const float* rewards   = (const float*)d_in[2];
    const float* values    = (const float*)d_in[3];
    int T = in_sizes[0];

    int nblocks = (T + OUT_CHUNK - 1) / OUT_CHUNK;
    if (nblocks > 4096) nblocks = 4096;   // g_partials capacity (T=2^23 -> 2048)

    ppo_fused<<<nblocks, THREADS>>>(probs, probs_old, rewards, values,
                                    (float*)d_out, T);
}